// round 1
// baseline (speedup 1.0000x reference)
#include <cuda_runtime.h>
#include <math.h>

#define BATCH 8192
#define HDIM  1024
#define GH    512
#define EMH   256
#define OUTD  18
#define GOUT  10

// -------- scratch (device globals: allocation-free) --------
__device__ float g_h0  [BATCH*HDIM];
__device__ float g_base[BATCH*HDIM];
__device__ float g_eh  [BATCH*EMH];
__device__ float g_gin [BATCH*HDIM];
__device__ float g_gh  [BATCH*GH];
__device__ float g_logits[BATCH*GOUT];
__device__ float g_gates [BATCH*GOUT];
__device__ float g_out0[BATCH*HDIM];
__device__ float g_out1[BATCH*HDIM];
__device__ float g_out2[BATCH*HDIM];
__device__ float g_out3[BATCH*HDIM];
__device__ float g_inp [BATCH*HDIM];
__device__ float g_last[BATCH*HDIM];

// =====================================================================
// Tiled SGEMM: C = epi( op(A) @ B + bias )
//   op(A): optional relu on A load
//   epi:   optional relu, then optional elementwise mul by Cmul
// BM=BN=128, BK=8, 8x8 per thread, 256 threads. Requires
// M%128==0, N%128==0, K%8==0 (true for all shapes here).
// =====================================================================
template<bool RELU_A, bool RELU_C, bool MUL_C>
__global__ __launch_bounds__(256)
void sgemm_kernel(const float* __restrict__ A, const float* __restrict__ Bm,
                  const float* __restrict__ bias, const float* __restrict__ Cmul,
                  float* __restrict__ C, int M, int N, int K)
{
    __shared__ float As[8][128];
    __shared__ float Bs[8][128];
    const int tid = threadIdx.x;
    const int bm = blockIdx.y * 128;
    const int bn = blockIdx.x * 128;

    const int arow = tid >> 1;          // 0..127
    const int acol = (tid & 1) << 2;    // 0 or 4
    const int brow = tid >> 5;          // 0..7
    const int bcol = (tid & 31) << 2;   // 0..124
    const int tx = (tid & 15) << 3;     // col offset within tile
    const int ty = (tid >> 4) << 3;     // row offset within tile

    float acc[8][8];
#pragma unroll
    for (int i = 0; i < 8; i++)
#pragma unroll
        for (int j = 0; j < 8; j++) acc[i][j] = 0.f;

    const float* Ap = A + (bm + arow) * K + acol;
    const float* Bp = Bm + brow * N + bn + bcol;

    for (int k0 = 0; k0 < K; k0 += 8) {
        float4 av = *(const float4*)(Ap + k0);
        if (RELU_A) {
            av.x = fmaxf(av.x, 0.f); av.y = fmaxf(av.y, 0.f);
            av.z = fmaxf(av.z, 0.f); av.w = fmaxf(av.w, 0.f);
        }
        As[acol + 0][arow] = av.x;
        As[acol + 1][arow] = av.y;
        As[acol + 2][arow] = av.z;
        As[acol + 3][arow] = av.w;
        *(float4*)&Bs[brow][bcol] = *(const float4*)(Bp + k0 * N);
        __syncthreads();
#pragma unroll
        for (int k = 0; k < 8; k++) {
            float ra[8], rb[8];
#pragma unroll
            for (int i = 0; i < 8; i++) ra[i] = As[k][ty + i];
#pragma unroll
            for (int j = 0; j < 8; j++) rb[j] = Bs[k][tx + j];
#pragma unroll
            for (int i = 0; i < 8; i++)
#pragma unroll
                for (int j = 0; j < 8; j++) acc[i][j] += ra[i] * rb[j];
        }
        __syncthreads();
    }

#pragma unroll
    for (int i = 0; i < 8; i++) {
        const int row = bm + ty + i;
#pragma unroll
        for (int j = 0; j < 8; j += 4) {
            const int col = bn + tx + j;
            float4 c;
            c.x = acc[i][j + 0] + bias[col + 0];
            c.y = acc[i][j + 1] + bias[col + 1];
            c.z = acc[i][j + 2] + bias[col + 2];
            c.w = acc[i][j + 3] + bias[col + 3];
            if (RELU_C) {
                c.x = fmaxf(c.x, 0.f); c.y = fmaxf(c.y, 0.f);
                c.z = fmaxf(c.z, 0.f); c.w = fmaxf(c.w, 0.f);
            }
            if (MUL_C) {
                const float4 mv = *(const float4*)(Cmul + row * N + col);
                c.x *= mv.x; c.y *= mv.y; c.z *= mv.z; c.w *= mv.w;
            }
            *(float4*)(C + row * N + col) = c;
        }
    }
}

// em hidden: eh[b,j] = relu(em[b]*em_W0[j] + em_b0[j])
__global__ void ehidden_kernel(const float* __restrict__ em, const float* __restrict__ W0,
                               const float* __restrict__ b0, float* __restrict__ eh)
{
    int idx = blockIdx.x * blockDim.x + threadIdx.x;
    if (idx >= BATCH * EMH) return;
    int b = idx >> 8;        // EMH = 256
    int j = idx & (EMH - 1);
    eh[idx] = fmaxf(em[b] * W0[j] + b0[j], 0.f);
}

// logits = gate_h @ gate_W1 + gate_b1   (N=10, simple per-element)
__global__ void logits_kernel(const float* __restrict__ gh, const float* __restrict__ W,
                              const float* __restrict__ b, float* __restrict__ logits)
{
    int idx = blockIdx.x * blockDim.x + threadIdx.x;
    if (idx >= BATCH * GOUT) return;
    int row = idx / GOUT, j = idx % GOUT;
    const float* g = gh + row * GH;
    float s = b[j];
    for (int k = 0; k < GH; k++) s += g[k] * W[k * GOUT + j];
    logits[idx] = s;
}

// Routing: top-2 + softmax gates per module group, matching jax.lax.top_k
// tie-breaking (lowest index first).
__device__ __forceinline__ void route_m(const float* l, int m,
                                        float* g, float* oh, float* sm)
{
    float mx = l[0];
    for (int i = 1; i < m; i++) mx = fmaxf(mx, l[i]);
    float e[4], s = 0.f;
    for (int i = 0; i < m; i++) { e[i] = expf(l[i] - mx); s += e[i]; }
    float inv = 1.f / s;
    for (int i = 0; i < m; i++) sm[i] = e[i] * inv;
    int i1 = 0;
    for (int i = 1; i < m; i++) if (l[i] > l[i1]) i1 = i;
    int i2 = -1;
    for (int i = 0; i < m; i++) {
        if (i == i1) continue;
        if (i2 < 0 || l[i] > l[i2]) i2 = i;
    }
    float m2 = fmaxf(l[i1], l[i2]);
    float ea = expf(l[i1] - m2), eb = expf(l[i2] - m2);
    float si = 1.f / (ea + eb);
    g[i1] = ea * si; g[i2] = eb * si;
    oh[i1] = 1.f; oh[i2] = 1.f;
}

__global__ void routing_kernel(const float* __restrict__ logits, float* __restrict__ gdev,
                               float* __restrict__ og, float* __restrict__ ooh,
                               float* __restrict__ osm)
{
    int b = blockIdx.x * blockDim.x + threadIdx.x;
    if (b >= BATCH) return;
    float l[GOUT];
#pragma unroll
    for (int i = 0; i < GOUT; i++) l[i] = logits[b * GOUT + i];
    float g[GOUT], oh[GOUT], sm[GOUT];
#pragma unroll
    for (int i = 0; i < GOUT; i++) { g[i] = 0.f; oh[i] = 0.f; sm[i] = 0.f; }
    // m=1: single module, gate=1
    g[0] = 1.f; oh[0] = 1.f; sm[0] = 1.f;
    route_m(l + 1, 2, g + 1, oh + 1, sm + 1);
    route_m(l + 3, 3, g + 3, oh + 3, sm + 3);
    route_m(l + 6, 4, g + 6, oh + 6, sm + 6);
#pragma unroll
    for (int i = 0; i < GOUT; i++) {
        gdev[b * GOUT + i] = g[i];
        og  [b * GOUT + i] = g[i];
        ooh [b * GOUT + i] = oh[i];
        osm [b * GOUT + i] = sm[i];
    }
}

// dst[b,:] = sum_t gates[b, goff+t] * o_t[b,:]   (float4 per thread)
__global__ void wsum_kernel(const float* __restrict__ gates, int goff, int nt,
                            const float* __restrict__ o0, const float* __restrict__ o1,
                            const float* __restrict__ o2, const float* __restrict__ o3,
                            float* __restrict__ dst)
{
    int idx = blockIdx.x * blockDim.x + threadIdx.x;    // float4 index
    if (idx >= BATCH * (HDIM / 4)) return;
    int b = idx / (HDIM / 4);
    const float* g = gates + b * GOUT + goff;
    float4 r = make_float4(0.f, 0.f, 0.f, 0.f);
    float w; float4 v;
    w = g[0]; v = ((const float4*)o0)[idx];
    r.x += w * v.x; r.y += w * v.y; r.z += w * v.z; r.w += w * v.w;
    if (nt > 1) {
        w = g[1]; v = ((const float4*)o1)[idx];
        r.x += w * v.x; r.y += w * v.y; r.z += w * v.z; r.w += w * v.w;
    }
    if (nt > 2) {
        w = g[2]; v = ((const float4*)o2)[idx];
        r.x += w * v.x; r.y += w * v.y; r.z += w * v.z; r.w += w * v.w;
    }
    if (nt > 3) {
        w = g[3]; v = ((const float4*)o3)[idx];
        r.x += w * v.x; r.y += w * v.y; r.z += w * v.z; r.w += w * v.w;
    }
    ((float4*)dst)[idx] = r;
}

// final = last_buf @ last_W + last_b   (N=18)
__global__ void final_kernel(const float* __restrict__ last, const float* __restrict__ W,
                             const float* __restrict__ b, float* __restrict__ out)
{
    int idx = blockIdx.x * blockDim.x + threadIdx.x;
    if (idx >= BATCH * OUTD) return;
    int row = idx / OUTD, o = idx % OUTD;
    const float4* lp = (const float4*)(last + row * HDIM);
    float s = 0.f;
    for (int k = 0; k < HDIM / 4; k++) {
        float4 v = lp[k];
        s += v.x * W[(4 * k + 0) * OUTD + o];
        s += v.y * W[(4 * k + 1) * OUTD + o];
        s += v.z * W[(4 * k + 2) * OUTD + o];
        s += v.w * W[(4 * k + 3) * OUTD + o];
    }
    out[idx] = s + b[o];
}

extern "C" void kernel_launch(void* const* d_in, const int* in_sizes, int n_in,
                              void* d_out, int out_size)
{
    const float* x        = (const float*)d_in[0];
    const float* em       = (const float*)d_in[1];
    const float* base_W0  = (const float*)d_in[2];
    const float* base_b0  = (const float*)d_in[3];
    const float* base_W1  = (const float*)d_in[4];
    const float* base_b1  = (const float*)d_in[5];
    const float* em_W0    = (const float*)d_in[6];
    const float* em_b0    = (const float*)d_in[7];
    const float* em_W1    = (const float*)d_in[8];
    const float* em_b1    = (const float*)d_in[9];
    const float* gate_W0  = (const float*)d_in[10];
    const float* gate_b0  = (const float*)d_in[11];
    const float* gate_W1  = (const float*)d_in[12];
    const float* gate_b1  = (const float*)d_in[13];
    const float* fc_W     = (const float*)d_in[14];
    const float* fc_b     = (const float*)d_in[15];
    const float* last_W   = (const float*)d_in[16];
    const float* last_b   = (const float*)d_in[17];
    float* out = (float*)d_out;

    float *h0, *base, *eh, *gin, *gh, *logits, *gates;
    float *o0, *o1, *o2, *o3, *inp, *last;
    cudaGetSymbolAddress((void**)&h0,   g_h0);
    cudaGetSymbolAddress((void**)&base, g_base);
    cudaGetSymbolAddress((void**)&eh,   g_eh);
    cudaGetSymbolAddress((void**)&gin,  g_gin);
    cudaGetSymbolAddress((void**)&gh,   g_gh);
    cudaGetSymbolAddress((void**)&logits, g_logits);
    cudaGetSymbolAddress((void**)&gates,  g_gates);
    cudaGetSymbolAddress((void**)&o0,  g_out0);
    cudaGetSymbolAddress((void**)&o1,  g_out1);
    cudaGetSymbolAddress((void**)&o2,  g_out2);
    cudaGetSymbolAddress((void**)&o3,  g_out3);
    cudaGetSymbolAddress((void**)&inp, g_inp);
    cudaGetSymbolAddress((void**)&last, g_last);

    const int OFF_G  = BATCH * OUTD;          // 147456
    const int OFF_OH = OFF_G + BATCH * GOUT;  // +81920
    const int OFF_SM = OFF_OH + BATCH * GOUT;

    const dim3 gridH (HDIM / 128, BATCH / 128);   // N=1024
    const dim3 gridGH(GH   / 128, BATCH / 128);   // N=512

    // 1) h0 = relu(x @ base_W0 + b0)
    sgemm_kernel<false, true,  false><<<gridH, 256>>>(x, base_W0, base_b0, nullptr, h0, BATCH, HDIM, 64);
    // 2) base_out = h0 @ base_W1 + b1
    sgemm_kernel<false, false, false><<<gridH, 256>>>(h0, base_W1, base_b1, nullptr, base, BATCH, HDIM, HDIM);
    // 3) eh = relu(em * em_W0 + em_b0)
    ehidden_kernel<<<(BATCH * EMH + 255) / 256, 256>>>(em, em_W0, em_b0, eh);
    // 4) gate_in = relu(eh @ em_W1 + em_b1) * base_out
    sgemm_kernel<false, true,  true ><<<gridH, 256>>>(eh, em_W1, em_b1, base, gin, BATCH, HDIM, EMH);
    // 5) gate_h = relu(gate_in @ gate_W0 + gate_b0)
    sgemm_kernel<false, true,  false><<<gridGH, 256>>>(gin, gate_W0, gate_b0, nullptr, gh, BATCH, GH, HDIM);
    // 6) logits
    logits_kernel<<<(BATCH * GOUT + 255) / 256, 256>>>(gh, gate_W1, gate_b1, logits);
    // 7) routing -> gates + (gates, onehot, soft) outputs
    routing_kernel<<<(BATCH + 255) / 256, 256>>>(logits, gates, out + OFF_G, out + OFF_OH, out + OFF_SM);
    // 8) out0 = relu(relu(base_out) @ fc_W0 + fc_b0)
    sgemm_kernel<true,  true,  false><<<gridH, 256>>>(base, fc_W, fc_b, nullptr, o0, BATCH, HDIM, HDIM);
    // 9) out1 = relu(out0 @ fc_W1 + fc_b1)   (gate for step1 is identically 1)
    sgemm_kernel<false, true,  false><<<gridH, 256>>>(o0, fc_W + 1 * HDIM * HDIM, fc_b + 1 * HDIM, nullptr, o1, BATCH, HDIM, HDIM);
    // 10) inp = g1*out0 + g2*out1 ; out2 = relu(inp @ fc_W2 + fc_b2)
    wsum_kernel<<<(BATCH * HDIM / 4 + 255) / 256, 256>>>(gates, 1, 2, o0, o1, nullptr, nullptr, inp);
    sgemm_kernel<false, true,  false><<<gridH, 256>>>(inp, fc_W + 2 * HDIM * HDIM, fc_b + 2 * HDIM, nullptr, o2, BATCH, HDIM, HDIM);
    // 11) inp = g3*out0 + g4*out1 + g5*out2 ; out3 = relu(inp @ fc_W3 + fc_b3)
    wsum_kernel<<<(BATCH * HDIM / 4 + 255) / 256, 256>>>(gates, 3, 3, o0, o1, o2, nullptr, inp);
    sgemm_kernel<false, true,  false><<<gridH, 256>>>(inp, fc_W + 3 * HDIM * HDIM, fc_b + 3 * HDIM, nullptr, o3, BATCH, HDIM, HDIM);
    // 12) last = sum g6..g9 * out0..3 ; final = last @ last_W + last_b
    wsum_kernel<<<(BATCH * HDIM / 4 + 255) / 256, 256>>>(gates, 6, 4, o0, o1, o2, o3, last);
    final_kernel<<<(BATCH * OUTD + 255) / 256, 256>>>(last, last_W, last_b, out);
}